// round 9
// baseline (speedup 1.0000x reference)
#include <cuda_runtime.h>
#include <math.h>

#define B_  8
#define T_  2048
#define C_  1024
#define H_  128
#define BT_ (B_*T_)

// Scratch: projected Q,K,V (tf32-rounded fp32) + pre-rounded weights
__device__ float g_q[BT_*H_];
__device__ float g_k[BT_*H_];
__device__ float g_v[BT_*H_];
__device__ float g_wr[3*H_*C_];   // [head][n][k], tf32-rounded

// ---------------------------------------------------------------------------
// helpers
// ---------------------------------------------------------------------------
__device__ __forceinline__ unsigned f2tf(float x) {
    unsigned r;
    asm("cvt.rna.tf32.f32 %0, %1;" : "=r"(r) : "f"(x));
    return r;
}
__device__ __forceinline__ float tfr(float x) { return __uint_as_float(f2tf(x)); }

__device__ __forceinline__ void mma_tf32(float* d, unsigned a0, unsigned a1,
                                         unsigned a2, unsigned a3,
                                         unsigned b0, unsigned b1) {
    asm volatile(
        "mma.sync.aligned.m16n8k8.row.col.f32.tf32.tf32.f32 "
        "{%0,%1,%2,%3},{%4,%5,%6,%7},{%8,%9},{%0,%1,%2,%3};"
        : "+f"(d[0]), "+f"(d[1]), "+f"(d[2]), "+f"(d[3])
        : "r"(a0), "r"(a1), "r"(a2), "r"(a3), "r"(b0), "r"(b1));
}

__device__ __forceinline__ void cp_async16(void* smem_dst, const void* gsrc) {
    unsigned s = (unsigned)__cvta_generic_to_shared(smem_dst);
    asm volatile("cp.async.cg.shared.global [%0], [%1], 16;" :: "r"(s), "l"(gsrc));
}
__device__ __forceinline__ void cp_commit() { asm volatile("cp.async.commit_group;"); }
__device__ __forceinline__ void cp_wait0()  { asm volatile("cp.async.wait_group 0;"); }
__device__ __forceinline__ void cp_wait1()  { asm volatile("cp.async.wait_group 1;"); }

// ---------------------------------------------------------------------------
// Kernel 0: pre-round W to tf32 (once per launch, ~3us).
// grid (128, 3), 256 threads; each thread handles exactly one float4.
// ---------------------------------------------------------------------------
__global__ __launch_bounds__(256) void round_w(
    const float* __restrict__ Wq,
    const float* __restrict__ Wk,
    const float* __restrict__ Wv)
{
    const int head = blockIdx.y;
    const float* __restrict__ W = (head == 0) ? Wq : (head == 1) ? Wk : Wv;
    const int idx = blockIdx.x * 256 + threadIdx.x;   // float4 index, 32768/head
    float4 v = ((const float4*)W)[idx];
    float4 r = make_float4(tfr(v.x), tfr(v.y), tfr(v.z), tfr(v.w));
    ((float4*)(g_wr + (size_t)head * H_ * C_))[idx] = r;
}

// ---------------------------------------------------------------------------
// Kernel 1: fused 3-head QKV projection, tf32 mma.sync.
// CTA: 128 rows of x, all 3 heads (N=384). 256 threads, 8 warps (2m x 4n),
// warp tile 64m x 96n, k-tile 32, cp.async double-buffered.
// grid = (BT/128) = 128 CTAs.
// ---------------------------------------------------------------------------
struct QkvSmem {
    float As[2][128][36];   // x tile, raw fp32 (cvt at frag load)
    float Bs[2][384][36];   // W tiles, pre-rounded tf32
};

__global__ __launch_bounds__(256, 1) void qkv_mma(const float* __restrict__ x)
{
    extern __shared__ __align__(16) char smem_raw[];
    QkvSmem& S = *reinterpret_cast<QkvSmem*>(smem_raw);

    const int tid  = threadIdx.x;
    const int lane = tid & 31;
    const int w    = tid >> 5;
    const int gid  = lane >> 2;
    const int tig  = lane & 3;

    const size_t m0 = (size_t)blockIdx.x * 128;
    const int wm = (w >> 2) * 64;     // 0 or 64
    const int wn = (w & 3) * 96;      // 0,96,192,288

    // loader mapping: 2 threads per 32-float row; thread covers 4 float4
    const int a_r = tid >> 1;         // 0..127
    const int a_c = (tid & 1) * 16;   // float col base

    float acc[4][12][4];
#pragma unroll
    for (int mf = 0; mf < 4; mf++)
#pragma unroll
        for (int nt = 0; nt < 12; nt++)
#pragma unroll
            for (int j = 0; j < 4; j++) acc[mf][nt][j] = 0.f;

    // prefetch k-tile 0
#pragma unroll
    for (int i = 0; i < 4; i++) {
        const int c = a_c + 4 * i;
        cp_async16(&S.As[0][a_r][c], &x[(m0 + a_r) * C_ + c]);
    }
#pragma unroll
    for (int h = 0; h < 3; h++)
#pragma unroll
        for (int i = 0; i < 4; i++) {
            const int c = a_c + 4 * i;
            cp_async16(&S.Bs[0][h * 128 + a_r][c],
                       &g_wr[(size_t)h * H_ * C_ + (size_t)a_r * C_ + c]);
        }
    cp_commit();

    for (int kt = 0; kt < 32; kt++) {
        const int k0 = kt * 32;
        if (kt < 31) {
            const int nb = (kt + 1) & 1;
            const int kn = k0 + 32;
#pragma unroll
            for (int i = 0; i < 4; i++) {
                const int c = a_c + 4 * i;
                cp_async16(&S.As[nb][a_r][c], &x[(m0 + a_r) * C_ + kn + c]);
            }
#pragma unroll
            for (int h = 0; h < 3; h++)
#pragma unroll
                for (int i = 0; i < 4; i++) {
                    const int c = a_c + 4 * i;
                    cp_async16(&S.Bs[nb][h * 128 + a_r][c],
                               &g_wr[(size_t)h * H_ * C_ + (size_t)a_r * C_ + kn + c]);
                }
            cp_commit();
            cp_wait1();
        } else {
            cp_wait0();
        }
        __syncthreads();
        const int cur = kt & 1;

#pragma unroll
        for (int ks = 0; ks < 4; ks++) {
            unsigned a[4][4];
#pragma unroll
            for (int mf = 0; mf < 4; mf++) {
                const int r = wm + mf * 16 + gid;
                a[mf][0] = f2tf(S.As[cur][r][ks * 8 + tig]);
                a[mf][1] = f2tf(S.As[cur][r + 8][ks * 8 + tig]);
                a[mf][2] = f2tf(S.As[cur][r][ks * 8 + tig + 4]);
                a[mf][3] = f2tf(S.As[cur][r + 8][ks * 8 + tig + 4]);
            }
#pragma unroll
            for (int nt = 0; nt < 12; nt++) {
                const int n = wn + nt * 8 + gid;
                unsigned b0 = __float_as_uint(S.Bs[cur][n][ks * 8 + tig]);
                unsigned b1 = __float_as_uint(S.Bs[cur][n][ks * 8 + tig + 4]);
#pragma unroll
                for (int mf = 0; mf < 4; mf++)
                    mma_tf32(acc[mf][nt], a[mf][0], a[mf][1], a[mf][2], a[mf][3], b0, b1);
            }
        }
        __syncthreads();
    }

    // epilogue: rna-round and store fp32 to the right head buffer
#pragma unroll
    for (int mf = 0; mf < 4; mf++) {
        const size_t r0 = m0 + wm + mf * 16 + gid;
#pragma unroll
        for (int nt = 0; nt < 12; nt++) {
            const int nbase = wn + nt * 8;
            const int head  = nbase >> 7;
            const int col   = (nbase & 127) + 2 * tig;
            float* __restrict__ outp = (head == 0) ? g_q : (head == 1) ? g_k : g_v;
            float2 v0 = make_float2(tfr(acc[mf][nt][0]), tfr(acc[mf][nt][1]));
            *(float2*)&outp[r0 * H_ + col] = v0;
            float2 v1 = make_float2(tfr(acc[mf][nt][2]), tfr(acc[mf][nt][3]));
            *(float2*)&outp[(r0 + 8) * H_ + col] = v1;
        }
    }
}

// ---------------------------------------------------------------------------
// Kernel 2: causal flash attention, tf32 mma.sync.
// Br = 128, Bc = 64, 8 warps (256 thr) sharing K/V tiles; warp w owns query
// rows [qt*128 + w*16, +16). Q frags + O register-resident. K/V double-
// buffered cp.async. grid = (16, 8).
// ---------------------------------------------------------------------------
struct AttnSmem {
    float Ks[2][64][132];   // K tiles (both bufs also used to stage Q halves)
    float Vs[2][64][136];   // V tiles
    float Ps[8][16][68];    // per-warp P relayout buffer
};

__global__ __launch_bounds__(256, 1) void attn_mma(float* __restrict__ out)
{
    extern __shared__ __align__(16) char smem_raw[];
    AttnSmem& S = *reinterpret_cast<AttnSmem*>(smem_raw);

    const int tid  = threadIdx.x;
    const int lane = tid & 31;
    const int w    = tid >> 5;       // 0..7
    const int gid  = lane >> 2;      // 0..7
    const int tig  = lane & 3;       // 0..3
    const int b    = blockIdx.y;
    const int qt   = blockIdx.x;     // 0..15
    const float scale = 0.08838834764831845f;   // 1/sqrt(128)

    const size_t qbase = ((size_t)b * T_ + (size_t)qt * 128) * H_;

    // loader mapping: 4 threads per 128-float row, 8 float4 each
    const int lr = tid >> 2;          // 0..63
    const int lc = (tid & 3) * 4;     // float col base; cols lc + 16*i

    // ---- stage Q tile (two 64-row halves) into Ks[0], Ks[1] ----
#pragma unroll
    for (int i = 0; i < 8; i++) {
        const int c = lc + 16 * i;
        cp_async16(&S.Ks[0][lr][c], &g_q[qbase + (size_t)lr * H_ + c]);
        cp_async16(&S.Ks[1][lr][c], &g_q[qbase + (size_t)(64 + lr) * H_ + c]);
    }
    cp_commit();
    cp_wait0();
    __syncthreads();

    unsigned qa[16][4];
    {
        const int half = w >> 2;
        const int rA   = (w & 3) * 16 + gid;
#pragma unroll
        for (int ks = 0; ks < 16; ks++) {
            qa[ks][0] = __float_as_uint(S.Ks[half][rA][ks * 8 + tig]);
            qa[ks][1] = __float_as_uint(S.Ks[half][rA + 8][ks * 8 + tig]);
            qa[ks][2] = __float_as_uint(S.Ks[half][rA][ks * 8 + tig + 4]);
            qa[ks][3] = __float_as_uint(S.Ks[half][rA + 8][ks * 8 + tig + 4]);
        }
    }
    __syncthreads();

    float o[16][4];
#pragma unroll
    for (int nt = 0; nt < 16; nt++)
#pragma unroll
        for (int j = 0; j < 4; j++) o[nt][j] = 0.f;
    float m_runA = -1e30f, m_runB = -1e30f;
    float l_runA = 0.f,    l_runB = 0.f;

    const int rowA   = qt * 128 + w * 16 + gid;
    const int rowB   = rowA + 8;
    const int rowMax = qt * 128 + w * 16 + 15;
    const int nkt    = 2 * qt + 2;

    // preload kt = 0
    {
        const size_t kb0 = ((size_t)b * T_) * H_;
#pragma unroll
        for (int i = 0; i < 8; i++) {
            const int c = lc + 16 * i;
            cp_async16(&S.Ks[0][lr][c], &g_k[kb0 + (size_t)lr * H_ + c]);
            cp_async16(&S.Vs[0][lr][c], &g_v[kb0 + (size_t)lr * H_ + c]);
        }
        cp_commit();
    }

    for (int kt = 0; kt < nkt; kt++) {
        if (kt + 1 < nkt) {
            const size_t kb = ((size_t)b * T_ + (size_t)(kt + 1) * 64) * H_;
            const int nb = (kt + 1) & 1;
#pragma unroll
            for (int i = 0; i < 8; i++) {
                const int c = lc + 16 * i;
                cp_async16(&S.Ks[nb][lr][c], &g_k[kb + (size_t)lr * H_ + c]);
                cp_async16(&S.Vs[nb][lr][c], &g_v[kb + (size_t)lr * H_ + c]);
            }
            cp_commit();
            cp_wait1();
        } else {
            cp_wait0();
        }
        __syncthreads();
        const int cur  = kt & 1;
        const bool act = (kt * 64 <= rowMax);   // skip fully-masked tiles

        if (act) {
            // ---- S = Q K^T ----
            float s[8][4];
#pragma unroll
            for (int nt = 0; nt < 8; nt++)
#pragma unroll
                for (int j = 0; j < 4; j++) s[nt][j] = 0.f;

#pragma unroll
            for (int ks = 0; ks < 16; ks++) {
#pragma unroll
                for (int nt = 0; nt < 8; nt++) {
                    const int n = nt * 8 + gid;
                    unsigned b0 = __float_as_uint(S.Ks[cur][n][ks * 8 + tig]);
                    unsigned b1 = __float_as_uint(S.Ks[cur][n][ks * 8 + tig + 4]);
                    mma_tf32(s[nt], qa[ks][0], qa[ks][1], qa[ks][2], qa[ks][3], b0, b1);
                }
            }

#pragma unroll
            for (int nt = 0; nt < 8; nt++)
#pragma unroll
                for (int j = 0; j < 4; j++) s[nt][j] *= scale;

            if (kt >= 2 * qt) {   // diagonal-region tiles need elementwise mask
#pragma unroll
                for (int nt = 0; nt < 8; nt++) {
                    const int c0 = kt * 64 + nt * 8 + 2 * tig;
                    if (c0     > rowA) s[nt][0] = -1e30f;
                    if (c0 + 1 > rowA) s[nt][1] = -1e30f;
                    if (c0     > rowB) s[nt][2] = -1e30f;
                    if (c0 + 1 > rowB) s[nt][3] = -1e30f;
                }
            }

            // ---- per-warp online softmax ----
            float mA = -1e30f, mB = -1e30f;
#pragma unroll
            for (int nt = 0; nt < 8; nt++) {
                mA = fmaxf(mA, fmaxf(s[nt][0], s[nt][1]));
                mB = fmaxf(mB, fmaxf(s[nt][2], s[nt][3]));
            }
            mA = fmaxf(mA, __shfl_xor_sync(0xffffffffu, mA, 1));
            mA = fmaxf(mA, __shfl_xor_sync(0xffffffffu, mA, 2));
            mB = fmaxf(mB, __shfl_xor_sync(0xffffffffu, mB, 1));
            mB = fmaxf(mB, __shfl_xor_sync(0xffffffffu, mB, 2));

            const float mnA = fmaxf(m_runA, mA);
            const float mnB = fmaxf(m_runB, mB);
            const float aA  = __expf(m_runA - mnA);
            const float aB  = __expf(m_runB - mnB);
            m_runA = mnA; m_runB = mnB;

            float sumA = 0.f, sumB = 0.f;
#pragma unroll
            for (int nt = 0; nt < 8; nt++) {
                float p0 = __expf(s[nt][0] - mnA);
                float p1 = __expf(s[nt][1] - mnA);
                float p2 = __expf(s[nt][2] - mnB);
                float p3 = __expf(s[nt][3] - mnB);
                sumA += p0 + p1;
                sumB += p2 + p3;
                *(float2*)&S.Ps[w][gid][nt * 8 + 2 * tig]     = make_float2(tfr(p0), tfr(p1));
                *(float2*)&S.Ps[w][gid + 8][nt * 8 + 2 * tig] = make_float2(tfr(p2), tfr(p3));
            }
            sumA += __shfl_xor_sync(0xffffffffu, sumA, 1);
            sumA += __shfl_xor_sync(0xffffffffu, sumA, 2);
            sumB += __shfl_xor_sync(0xffffffffu, sumB, 1);
            sumB += __shfl_xor_sync(0xffffffffu, sumB, 2);
            l_runA = l_runA * aA + sumA;
            l_runB = l_runB * aB + sumB;

#pragma unroll
            for (int nt = 0; nt < 16; nt++) {
                o[nt][0] *= aA; o[nt][1] *= aA;
                o[nt][2] *= aB; o[nt][3] *= aB;
            }
            __syncwarp();

            // ---- O += P V ----
#pragma unroll
            for (int k8 = 0; k8 < 8; k8++) {
                unsigned a0 = __float_as_uint(S.Ps[w][gid][k8 * 8 + tig]);
                unsigned a1 = __float_as_uint(S.Ps[w][gid + 8][k8 * 8 + tig]);
                unsigned a2 = __float_as_uint(S.Ps[w][gid][k8 * 8 + tig + 4]);
                unsigned a3 = __float_as_uint(S.Ps[w][gid + 8][k8 * 8 + tig + 4]);
#pragma unroll
                for (int nt = 0; nt < 16; nt++) {
                    unsigned b0 = __float_as_uint(S.Vs[cur][k8 * 8 + tig][nt * 8 + gid]);
                    unsigned b1 = __float_as_uint(S.Vs[cur][k8 * 8 + tig + 4][nt * 8 + gid]);
                    mma_tf32(o[nt], a0, a1, a2, a3, b0, b1);
                }
            }
        }
        __syncthreads();
    }

    // ---- final normalize + write ----
    const float iA = 1.f / l_runA;
    const float iB = 1.f / l_runB;
    const size_t obA = ((size_t)b * T_ + rowA) * H_;
    const size_t obB = ((size_t)b * T_ + rowB) * H_;
#pragma unroll
    for (int nt = 0; nt < 16; nt++) {
        const int c = nt * 8 + 2 * tig;
        *(float2*)&out[obA + c] = make_float2(o[nt][0] * iA, o[nt][1] * iA);
        *(float2*)&out[obB + c] = make_float2(o[nt][2] * iB, o[nt][3] * iB);
    }
}

// ---------------------------------------------------------------------------
extern "C" void kernel_launch(void* const* d_in, const int* in_sizes, int n_in,
                              void* d_out, int out_size)
{
    const float* x  = (const float*)d_in[0];
    const float* Wq = (const float*)d_in[1];
    const float* Wk = (const float*)d_in[2];
    const float* Wv = (const float*)d_in[3];
    float* out = (float*)d_out;

    static int attr_set = 0;
    if (!attr_set) {
        cudaFuncSetAttribute(qkv_mma,
                             cudaFuncAttributeMaxDynamicSharedMemorySize,
                             (int)sizeof(QkvSmem));
        cudaFuncSetAttribute(attn_mma,
                             cudaFuncAttributeMaxDynamicSharedMemorySize,
                             (int)sizeof(AttnSmem));
        attr_set = 1;
    }

    {
        dim3 grid(128, 3);
        round_w<<<grid, 256>>>(Wq, Wk, Wv);
    }
    {
        dim3 grid(BT_ / 128);
        qkv_mma<<<grid, 256, (int)sizeof(QkvSmem)>>>(x);
    }
    {
        dim3 grid(16, B_);
        attn_mma<<<grid, 256, (int)sizeof(AttnSmem)>>>(out);
    }
}